// round 3
// baseline (speedup 1.0000x reference)
#include <cuda_runtime.h>

#define EPSB 1e-5f
#define NB 16

// ---------------- device-global scratch (no allocation allowed) ----------------
// activation ping-pong buffers, NHWC uint8 (quant codes 0..15)
__device__ __align__(128) unsigned char g_actA[NB * 160 * 320 * 16]; // 13.1 MB (max: block0 out)
__device__ __align__(128) unsigned char g_actB[NB * 80 * 160 * 32];  //  6.6 MB (max: block1 out)

// packed int8x4 quantized weights, layout per weight: [tap][cin4][cout] (int32 word = 4 input chans)
__device__ int   g_wq[52560];
__device__ float g_sw[9];        // per-tensor weight scales
__device__ float g_A[512];       // per-block (8) x per-channel (<=64) epilogue scale
__device__ float g_B[512];       // per-block bias
__device__ float g_head_sc;      // s_w9 * scales[9]

// ---------------- prep kernels ----------------
struct MaxArgs { const float* p[9]; int n[9]; };

__global__ void k_maxabs(MaxArgs a) {
    __shared__ float red[8];
    const int b = blockIdx.x;
    const float* __restrict__ w = a.p[b];
    const int n = a.n[b];
    float m = 0.f;
    for (int i = threadIdx.x; i < n; i += blockDim.x) m = fmaxf(m, fabsf(w[i]));
    for (int s = 16; s; s >>= 1) m = fmaxf(m, __shfl_xor_sync(0xffffffffu, m, s));
    if ((threadIdx.x & 31) == 0) red[threadIdx.x >> 5] = m;
    __syncthreads();
    if (threadIdx.x < 32) {
        float v = (threadIdx.x < 8) ? red[threadIdx.x] : 0.f;
        for (int s = 4; s; s >>= 1) v = fmaxf(v, __shfl_xor_sync(0xffffffffu, v, s));
        if (threadIdx.x == 0) g_sw[b] = v / 7.0f;
    }
}

struct PackArgs { const float* w[9]; };

__global__ void k_pack(PackArgs a) {
    const int off[10]  = {0, 144, 1296, 5904, 15120, 24336, 33552, 42768, 51984, 52560};
    const int cinR[9]  = {3, 16, 32, 64, 64, 64, 64, 64, 64};
    const int cin4[9]  = {1, 4, 8, 16, 16, 16, 16, 16, 16};
    const int coutA[9] = {16, 32, 64, 64, 64, 64, 64, 64, 36};
    const int kk[9]    = {3, 3, 3, 3, 3, 3, 3, 3, 1};

    int idx = blockIdx.x * blockDim.x + threadIdx.x;
    if (idx >= 52560) return;
    int wi = 0;
    while (wi < 8 && idx >= off[wi + 1]) wi++;
    const int local = idx - off[wi];
    const int C4 = cin4[wi], CO = coutA[wi], K = kk[wi], CR = cinR[wi];
    const int tap = local / (C4 * CO);
    const int rest = local % (C4 * CO);
    const int c4 = rest / CO, o = rest % CO;
    const int ky = tap / K, kx = tap % K;
    const float s = g_sw[wi];
    const float* __restrict__ w = a.w[wi];
    unsigned packed = 0;
#pragma unroll
    for (int j = 0; j < 4; j++) {
        const int ci = c4 * 4 + j;
        int q = 0;
        if (ci < CR) {
            float v = w[((o * CR + ci) * K + ky) * K + kx];
            q = __float2int_rn(__fdiv_rn(v, s));
            q = min(7, max(-7, q));
        }
        packed |= (unsigned)(q & 255) << (j * 8);
    }
    g_wq[idx] = (int)packed;
}

struct BnArgs { const float* bn[8]; const float* scales; };

__global__ void k_params(BnArgs a) {
    const int couts[8] = {16, 32, 64, 64, 64, 64, 64, 64};
    for (int idx = threadIdx.x; idx < 8 * 64; idx += blockDim.x) {
        const int blk = idx >> 6, c = idx & 63;
        const int C = couts[blk];
        if (c >= C) continue;
        const float* __restrict__ bn = a.bn[blk];
        const float g = bn[c], b = bn[C + c], m = bn[2 * C + c], v = bn[3 * C + c];
        const float inv = __fdiv_rn(g, sqrtf(v + EPSB));
        const float s_in = a.scales[1 + blk];
        const float s_relu = a.scales[10 + blk];
        const float sw = g_sw[blk];
        g_A[idx] = __fdiv_rn(sw * s_in * inv, s_relu);
        g_B[idx] = __fdiv_rn(b - m * inv, s_relu);
    }
    if (threadIdx.x == 0) g_head_sc = g_sw[8] * a.scales[9];
}

// ---------------- generic fused conv block ----------------
// 3x3 SAME conv on int4 codes (dp4a), BN+ReLU+requant epilogue, optional 2x2 maxpool.
// Tile: 16x16 pre-pool output pixels, 256 threads (1 thread = 1 pixel, acc[COUT] in regs).
// Lane quads (lane&3) map to 2x2 pixel blocks so pooling is two shfl_xor's.
template <int CIN4, int COUT, bool POOL>
__global__ __launch_bounds__(256) void
k_conv(int inSel, int outSel, int woff, const float* __restrict__ scales,
       int sPrev, int sCur, int blk, int H, int W)
{
    constexpr int CIN = CIN4 * 4;
    constexpr int XS  = CIN4 + 1;          // +1 word pad: conflict-mitigating stride
    constexpr int NW  = 9 * CIN4 * COUT;

    extern __shared__ int smem[];
    int*   sw_  = smem;                     // weights [tap][c4][o]
    int*   sx   = smem + NW;                // input tile 18x18, packed int8x4
    float* sA   = (float*)(sx + 324 * XS);
    float* sB   = sA + COUT;
    int*   slut = (int*)(sB + COUT);        // 16-entry requant LUT

    const unsigned char* __restrict__ in  = inSel  ? g_actB : g_actA;
    unsigned char*       __restrict__ out = outSel ? g_actB : g_actA;
    const int* __restrict__ wq = g_wq + woff;

    const int tid = threadIdx.x;
    if (tid < 16) {
        const float sp = scales[sPrev], sc = scales[sCur];
        int v = __float2int_rn(__fdiv_rn((float)tid * sp, sc));
        slut[tid] = min(7, max(-8, v));
    }
    if (tid < COUT) { sA[tid] = g_A[blk * 64 + tid]; sB[tid] = g_B[blk * 64 + tid]; }
    for (int i = tid; i < NW; i += 256) sw_[i] = wq[i];
    __syncthreads();

    const int b  = blockIdx.z;
    const int x0 = blockIdx.x * 16, y0 = blockIdx.y * 16;

    // cooperative halo tile load + LUT requant + pack
    for (int i = tid; i < 324 * CIN4; i += 256) {
        const int pix = i / CIN4, c4 = i % CIN4;
        const int ty = pix / 18, tx = pix % 18;
        const int iy = y0 + ty - 1, ix = x0 + tx - 1;
        unsigned pkd = 0;
        if (iy >= 0 && iy < H && ix >= 0 && ix < W) {
            const uchar4 r = *reinterpret_cast<const uchar4*>(
                in + ((size_t)(b * H + iy) * W + ix) * CIN + c4 * 4);
            pkd =  (unsigned)(slut[r.x] & 255)
                | ((unsigned)(slut[r.y] & 255) << 8)
                | ((unsigned)(slut[r.z] & 255) << 16)
                | ((unsigned)(slut[r.w] & 255) << 24);
        }
        sx[pix * XS + c4] = (int)pkd;
    }
    __syncthreads();

    const int lane = tid & 31, warp = tid >> 5;
    const int quad = (warp << 3) + (lane >> 2);
    const int px = ((quad & 7) << 1) + (lane & 1);
    const int py = ((quad >> 3) << 1) + ((lane >> 1) & 1);

    int acc[COUT];
#pragma unroll
    for (int o = 0; o < COUT; o++) acc[o] = 0;

#pragma unroll
    for (int ky = 0; ky < 3; ky++)
#pragma unroll
    for (int kx = 0; kx < 3; kx++) {
        const int* __restrict__ xr = sx + ((py + ky) * 18 + (px + kx)) * XS;
        const int* __restrict__ wp = sw_ + (ky * 3 + kx) * CIN4 * COUT;
        for (int c4 = 0; c4 < CIN4; c4++) {
            const int xw = xr[c4];                 // register-cached across o-loop
            const int* __restrict__ w = wp + c4 * COUT;
#pragma unroll
            for (int o = 0; o < COUT; o += 4) {    // LDS.128 broadcast weight loads
                const int4 w4 = *reinterpret_cast<const int4*>(w + o);
                acc[o + 0] = __dp4a(xw, w4.x, acc[o + 0]);
                acc[o + 1] = __dp4a(xw, w4.y, acc[o + 1]);
                acc[o + 2] = __dp4a(xw, w4.z, acc[o + 2]);
                acc[o + 3] = __dp4a(xw, w4.w, acc[o + 3]);
            }
        }
    }

    unsigned pk[COUT / 4];
#pragma unroll
    for (int o = 0; o < COUT; o++) {
        const float y = (float)acc[o] * sA[o] + sB[o];
        int q = __float2int_rn(y);
        q = min(15, max(0, q));
        if (POOL) {
            q = max(q, __shfl_xor_sync(0xffffffffu, q, 1));
            q = max(q, __shfl_xor_sync(0xffffffffu, q, 2));
        }
        if ((o & 3) == 0) pk[o >> 2] = (unsigned)q;
        else              pk[o >> 2] |= (unsigned)q << ((o & 3) * 8);
    }

    const int gx = x0 + px, gy = y0 + py;
    if (POOL) {
        if ((lane & 3) == 0 && gy < H && gx < W) {
            const int Ho = H >> 1, Wo = W >> 1;
            uint4* dst = reinterpret_cast<uint4*>(
                out + ((size_t)(b * Ho + (gy >> 1)) * Wo + (gx >> 1)) * COUT);
#pragma unroll
            for (int j = 0; j < COUT / 16; j++)
                dst[j] = make_uint4(pk[4 * j], pk[4 * j + 1], pk[4 * j + 2], pk[4 * j + 3]);
        }
    } else {
        if (gy < H && gx < W) {
            uint4* dst = reinterpret_cast<uint4*>(
                out + ((size_t)(b * H + gy) * W + gx) * COUT);
#pragma unroll
            for (int j = 0; j < COUT / 16; j++)
                dst[j] = make_uint4(pk[4 * j], pk[4 * j + 1], pk[4 * j + 2], pk[4 * j + 3]);
        }
    }
}

// ---------------- block 0: float NCHW input, double quant (s0 then s1), 3ch->16ch, pool ----------------
__global__ __launch_bounds__(256) void
k_conv_first(const float* __restrict__ xin, const float* __restrict__ scales, int H, int W)
{
    constexpr int COUT = 16;
    __shared__ int   sw_[144];
    __shared__ int   sx[324 * 2];
    __shared__ float sA[16], sB[16];

    unsigned char* __restrict__ out = g_actA;
    const int tid = threadIdx.x;
    if (tid < 16) { sA[tid] = g_A[tid]; sB[tid] = g_B[tid]; }
    for (int i = tid; i < 144; i += 256) sw_[i] = g_wq[i];

    const float s0 = __ldg(&scales[0]);
    const float s1 = __ldg(&scales[1]);
    const int b = blockIdx.z;
    const int x0 = blockIdx.x * 16, y0 = blockIdx.y * 16;

    for (int i = tid; i < 324; i += 256) {
        const int ty = i / 18, tx = i % 18;
        const int iy = y0 + ty - 1, ix = x0 + tx - 1;
        unsigned pkd = 0;
        if (iy >= 0 && iy < H && ix >= 0 && ix < W) {
            const size_t base = (size_t)b * 3 * H * W + (size_t)iy * W + ix;
#pragma unroll
            for (int c = 0; c < 3; c++) {
                const float f = xin[base + (size_t)c * H * W];
                int v = __float2int_rn(__fdiv_rn(f, s0));
                v = min(7, max(-8, v));
                const float t = (float)v * s0;
                int v2 = __float2int_rn(__fdiv_rn(t, s1));
                v2 = min(7, max(-8, v2));
                pkd |= (unsigned)(v2 & 255) << (8 * c);
            }
        }
        sx[i * 2] = (int)pkd;
    }
    __syncthreads();

    const int lane = tid & 31, warp = tid >> 5;
    const int quad = (warp << 3) + (lane >> 2);
    const int px = ((quad & 7) << 1) + (lane & 1);
    const int py = ((quad >> 3) << 1) + ((lane >> 1) & 1);

    int acc[COUT];
#pragma unroll
    for (int o = 0; o < COUT; o++) acc[o] = 0;

#pragma unroll
    for (int ky = 0; ky < 3; ky++)
#pragma unroll
    for (int kx = 0; kx < 3; kx++) {
        const int xw = sx[((py + ky) * 18 + (px + kx)) * 2];
        const int* __restrict__ w = sw_ + (ky * 3 + kx) * COUT;
#pragma unroll
        for (int o = 0; o < COUT; o += 4) {
            const int4 w4 = *reinterpret_cast<const int4*>(w + o);
            acc[o + 0] = __dp4a(xw, w4.x, acc[o + 0]);
            acc[o + 1] = __dp4a(xw, w4.y, acc[o + 1]);
            acc[o + 2] = __dp4a(xw, w4.z, acc[o + 2]);
            acc[o + 3] = __dp4a(xw, w4.w, acc[o + 3]);
        }
    }

    unsigned pk[COUT / 4];
#pragma unroll
    for (int o = 0; o < COUT; o++) {
        const float y = (float)acc[o] * sA[o] + sB[o];
        int q = __float2int_rn(y);
        q = min(15, max(0, q));
        q = max(q, __shfl_xor_sync(0xffffffffu, q, 1));
        q = max(q, __shfl_xor_sync(0xffffffffu, q, 2));
        if ((o & 3) == 0) pk[o >> 2] = (unsigned)q;
        else              pk[o >> 2] |= (unsigned)q << ((o & 3) * 8);
    }

    const int gx = x0 + px, gy = y0 + py;
    if ((lane & 3) == 0 && gy < H && gx < W) {
        const int Ho = H >> 1, Wo = W >> 1;
        uint4* dst = reinterpret_cast<uint4*>(
            out + ((size_t)(b * Ho + (gy >> 1)) * Wo + (gx >> 1)) * COUT);
        dst[0] = make_uint4(pk[0], pk[1], pk[2], pk[3]);
    }
}

// ---------------- head: requant + 1x1 conv (64->36) + bias, fp32 NCHW out ----------------
__global__ __launch_bounds__(256) void
k_head(float* __restrict__ outp, const float* __restrict__ scales, const float* __restrict__ b9)
{
    __shared__ int   sw_[576];
    __shared__ int   slut[16];
    __shared__ float s_sc;
    const int tid = threadIdx.x;
    if (tid < 16) {
        const float sp = scales[17], sc = scales[9];
        int v = __float2int_rn(__fdiv_rn((float)tid * sp, sc));
        slut[tid] = min(7, max(-8, v));
    }
    if (tid == 0) s_sc = g_head_sc;
    for (int i = tid; i < 576; i += 256) sw_[i] = g_wq[51984 + i];
    __syncthreads();

    const int p = blockIdx.x * 256 + tid;      // 0..12799 = b*800 + y*40 + x
    if (p >= 12800) return;
    const int b = p / 800, rem = p % 800;
    const unsigned char* __restrict__ src = g_actB + (size_t)p * 64;

    int xw[16];
#pragma unroll
    for (int c4 = 0; c4 < 16; c4++) {
        const uchar4 r = *reinterpret_cast<const uchar4*>(src + c4 * 4);
        xw[c4] =  (slut[r.x] & 255) | ((slut[r.y] & 255) << 8)
               | ((slut[r.z] & 255) << 16) | ((slut[r.w] & 255) << 24);
    }
    int acc[36];
#pragma unroll
    for (int o = 0; o < 36; o++) acc[o] = 0;
#pragma unroll
    for (int c4 = 0; c4 < 16; c4++) {
        const int x = xw[c4];
        const int* __restrict__ w = sw_ + c4 * 36;
#pragma unroll
        for (int o = 0; o < 36; o++) acc[o] = __dp4a(x, w[o], acc[o]);
    }
    const float sc = s_sc;
#pragma unroll
    for (int o = 0; o < 36; o++)
        outp[(size_t)(b * 36 + o) * 800 + rem] = (float)acc[o] * sc + __ldg(&b9[o]);
}

// ---------------- launch ----------------
extern "C" void kernel_launch(void* const* d_in, const int* in_sizes, int n_in,
                              void* d_out, int out_size)
{
    const float* x      = (const float*)d_in[0];
    const float* b9     = (const float*)d_in[10];
    const float* scales = (const float*)d_in[19];

    const int wn[9] = {432, 4608, 18432, 36864, 36864, 36864, 36864, 36864, 2304};

    MaxArgs ma;
    for (int i = 0; i < 9; i++) { ma.p[i] = (const float*)d_in[1 + i]; ma.n[i] = wn[i]; }
    k_maxabs<<<9, 256>>>(ma);

    PackArgs pa;
    for (int i = 0; i < 9; i++) pa.w[i] = (const float*)d_in[1 + i];
    k_pack<<<(52560 + 255) / 256, 256>>>(pa);

    BnArgs ba;
    for (int i = 0; i < 8; i++) ba.bn[i] = (const float*)d_in[11 + i];
    ba.scales = scales;
    k_params<<<1, 256>>>(ba);

    // 59472 B dynamic smem > 48KB default: opt in (idempotent, capture-safe host call)
    cudaFuncSetAttribute(k_conv<16, 64, true>,  cudaFuncAttributeMaxDynamicSharedMemorySize, 59472);
    cudaFuncSetAttribute(k_conv<16, 64, false>, cudaFuncAttributeMaxDynamicSharedMemorySize, 59472);

    //                        grid                         smem   in out  woff           sP sC blk  H    W
    k_conv_first       <<<dim3(40, 20, 16), 256>>>(x, scales, 320, 640);
    k_conv<4,  32, true ><<<dim3(20, 10, 16), 256, 11408>>>(0, 1,   144, scales, 10, 2, 1, 160, 320);
    k_conv<8,  64, true ><<<dim3(10,  5, 16), 256, 30672>>>(1, 0,  1296, scales, 11, 3, 2,  80, 160);
    k_conv<16, 64, true ><<<dim3( 5,  3, 16), 256, 59472>>>(0, 1,  5904, scales, 12, 4, 3,  40,  80);
    k_conv<16, 64, false><<<dim3( 3,  2, 16), 256, 59472>>>(1, 0, 15120, scales, 13, 5, 4,  20,  40);
    k_conv<16, 64, false><<<dim3( 3,  2, 16), 256, 59472>>>(0, 1, 24336, scales, 14, 6, 5,  20,  40);
    k_conv<16, 64, false><<<dim3( 3,  2, 16), 256, 59472>>>(1, 0, 33552, scales, 15, 7, 6,  20,  40);
    k_conv<16, 64, false><<<dim3( 3,  2, 16), 256, 59472>>>(0, 1, 42768, scales, 16, 8, 7,  20,  40);
    k_head<<<50, 256>>>((float*)d_out, scales, b9);
}